// round 17
// baseline (speedup 1.0000x reference)
#include <cuda_runtime.h>
#include <cuda_fp16.h>
#include <cstdint>
#include <cstddef>

#define DEV __device__ __forceinline__

static constexpr int Bn = 8192;   // batch rows
static constexpr int Dd = 2048;   // model dim (K of GEMMs, N of V GEMM)
static constexpr int Ff = 1024;   // feature dim (N of Q/K GEMMs)

// ---------------- scratch (device globals: allocation-free) ----------------
__device__ __half g_Qh [(size_t)Bn * Dd];   // 32 MB
__device__ __half g_Kh [(size_t)Bn * Dd];   // 32 MB
__device__ __half g_Vh [(size_t)Bn * Dd];   // 32 MB
__device__ __half g_WqT[(size_t)Ff * Dd];   // [F][D] 4 MB
__device__ __half g_WkT[(size_t)Ff * Dd];   // [F][D] 4 MB
__device__ __half g_WvT[(size_t)Dd * Dd];   // [D][D] 8 MB
__device__ float g_sQ[Bn];
__device__ float g_sK[Bn];
__device__ float g_qk[Bn];
__device__ int   g_done_m[128];   // per-64-row-group QK completion (target 8)
__device__ int   g_c_wqk;         // Wq/Wk transpose blocks done (target 1024)
__device__ int   g_c_wv;          // Wv transpose blocks done (target 1024)
__device__ int   g_c_aqk[128];    // Q/K f2h blocks per 64-row group (target 16)
__device__ int   g_c_av[64];      // V f2h blocks per 128-row group (target 16)

// ---------------- helpers ----------------
DEV uint32_t smem_u32(const void* p) {
  uint32_t a;
  asm("{ .reg .u64 t; cvta.to.shared.u64 t, %1; cvt.u32.u64 %0, t; }" : "=r"(a) : "l"(p));
  return a;
}
DEV void cp16(uint32_t dst, const void* src) {
  asm volatile("cp.async.cg.shared.global [%0], [%1], 16;" :: "r"(dst), "l"(src));
}
DEV void cp_commit() { asm volatile("cp.async.commit_group;" ::: "memory"); }
DEV void cp_wait0()  { asm volatile("cp.async.wait_group 0;" ::: "memory"); }
DEV void cp_wait1()  { asm volatile("cp.async.wait_group 1;" ::: "memory"); }

// mma m16n8k16 fp16 (fp32 acc)
DEV void mma16(float c[4], const uint32_t a[4], const uint32_t b[2]) {
  asm volatile(
    "mma.sync.aligned.m16n8k16.row.col.f32.f16.f16.f32 "
    "{%0,%1,%2,%3}, {%4,%5,%6,%7}, {%8,%9}, {%0,%1,%2,%3};"
    : "+f"(c[0]), "+f"(c[1]), "+f"(c[2]), "+f"(c[3])
    : "r"(a[0]), "r"(a[1]), "r"(a[2]), "r"(a[3]), "r"(b[0]), "r"(b[1]));
}

// ldmatrix x4
DEV void ldsm4(uint32_t* r, uint32_t addr) {
  asm volatile("ldmatrix.sync.aligned.m8n8.x4.shared.b16 {%0,%1,%2,%3}, [%4];"
               : "=r"(r[0]), "=r"(r[1]), "=r"(r[2]), "=r"(r[3]) : "r"(addr));
}

DEV float elu_f(float x) { return x > 0.f ? x : expm1f(x); }
DEV uint32_t f2h2(float x, float y) {
  __half2 h = __floats2half2_rn(x, y);
  return *reinterpret_cast<uint32_t*>(&h);
}
DEV float ldcg(const float* p) {
  float v;
  asm volatile("ld.global.cg.f32 %0, [%1];" : "=f"(v) : "l"(p));
  return v;
}
DEV int ldcgi(const int* p) {
  int v;
  asm volatile("ld.global.cg.b32 %0, [%1];" : "=r"(v) : "l"(p));
  return v;
}
DEV void waitc(const int* p, int target) {
  int d;
  do {
    d = ldcgi(p);
    if (d < target) asm volatile("nanosleep.u32 128;");
  } while (d < target);
}

// Smem rows: 64 k-halves (128 B data) padded to 72 halves (144 B = 9*16 B).
static constexpr int ROWH = 72;
static constexpr int ROWB = 144;
static constexpr int EPIW = 136;   // QK epilogue staging row width (floats)

// ---------------- init kernel (zero counters + reduction buffers) ----------
__global__ void init_kernel() {
  int i = blockIdx.x * blockDim.x + threadIdx.x;
  if (i < Bn) { g_sQ[i] = 0.f; g_sK[i] = 0.f; g_qk[i] = 0.f; }
  if (i < 128) { g_done_m[i] = 0; g_c_aqk[i] = 0; }
  if (i < 64) g_c_av[i] = 0;
  if (i == 0) { g_c_wqk = 0; g_c_wv = 0; }
}

// ---------------- mega kernel ----------------
// Dispatch ranges (all waits reference strictly earlier-indexed producers):
//  [0,1024):      Wq/Wk transpose, 4 (32x32) tiles/block  -> g_c_wqk
//  [1024,3072):   Q+K f2h, 4 rows each/block              -> g_c_aqk[row/64]
//  [3072,4096):   Wv transpose, 4 tiles/block             -> g_c_wv
//  [4096,5120):   V f2h, 8 rows/block                     -> g_c_av[row/128]
//  [5120,6144):   QK gemm (R16 body) waits wqk + aqk[mg]  -> g_done_m[mg]
//  [6144,7168):   V gemm (R16 body) waits wv + av[g]; epilogue waits done_m
static constexpr int WQK_N  = 1024;
static constexpr int AQK_N  = 2048;
static constexpr int WV_N   = 1024;
static constexpr int AV_N   = 1024;
static constexpr int QK_N   = 1024;
static constexpr int V_N    = 1024;
static constexpr int B_WQK = 0;
static constexpr int B_AQK = B_WQK + WQK_N;       // 1024
static constexpr int B_WV  = B_AQK + AQK_N;       // 3072
static constexpr int B_AV  = B_WV + WV_N;         // 4096
static constexpr int B_QK  = B_AV + AV_N;         // 5120
static constexpr int B_V   = B_QK + QK_N;         // 6144
static constexpr int TOTAL_BLOCKS = B_V + V_N;    // 7168

static constexpr int QK_STAGE = (128 + 256) * ROWB;       // 55296
static constexpr int QK_SMEM  = 2 * QK_STAGE;             // 110592
static constexpr int TILE_B   = 128 * ROWB;               // 18432
static constexpr int V_STAGE  = 2 * TILE_B;               // 36864
static constexpr int V_SMEM   = 3 * V_STAGE;              // 110592
static constexpr int G_SMEM   = (QK_SMEM > V_SMEM) ? QK_SMEM : V_SMEM;
static constexpr int N_PER_MG = Ff / 128;                 // 8

__global__ void __launch_bounds__(256, 2)
mega_kernel(const float* __restrict__ Q, const float* __restrict__ K,
            const float* __restrict__ V, const float* __restrict__ Wq,
            const float* __restrict__ Wk, const float* __restrict__ Wv,
            const float* __restrict__ bq, const float* __restrict__ bk,
            const float* __restrict__ bv, float* __restrict__ out)
{
  extern __shared__ __align__(128) char smem[];
  const uint32_t sb = smem_u32(smem);
  const int tid = threadIdx.x;
  const int bx = blockIdx.x;

  if (bx < B_AQK) {
    // ============ Wq / Wk transpose: 4 tiles per block ============
    float* tile = reinterpret_cast<float*>(smem);    // 32 x 33 floats
    const int z = bx >> 9;                 // 0 = Wq, 1 = Wk
    const int b = bx & 511;
    const float* src = z ? Wk : Wq;
    __half* dst = z ? g_WkT : g_WqT;
    const int tx = tid & 31, ty = tid >> 5;          // 32 x 8
    #pragma unroll
    for (int tt = 0; tt < 4; ++tt) {
      const int t = b * 4 + tt;                      // 0..2047
      const int c0 = (t & 31) * 32, r0 = (t >> 5) * 32;
      __syncthreads();
      #pragma unroll
      for (int i = 0; i < 32; i += 8)
        tile[(ty + i) * 33 + tx] = src[(size_t)(r0 + ty + i) * Ff + (c0 + tx)];
      __syncthreads();
      #pragma unroll
      for (int i = 0; i < 32; i += 8)
        dst[(size_t)(c0 + ty + i) * Dd + (r0 + tx)] =
            __float2half_rn(tile[tx * 33 + ty + i]);
    }
    __threadfence();
    __syncthreads();
    if (tid == 0) atomicAdd(&g_c_wqk, 1);

  } else if (bx < B_WV) {
    // ============ Q + K f2h: 4 rows each per block ============
    const int b = bx - B_AQK;              // 0..2047, rows 4b..4b+3
    #pragma unroll
    for (int r = 0; r < 4; ++r) {
      const size_t off = ((size_t)(b * 4 + r)) * Dd + tid * 8;
      float4 qa = *reinterpret_cast<const float4*>(Q + off);
      float4 qb = *reinterpret_cast<const float4*>(Q + off + 4);
      float4 ka = *reinterpret_cast<const float4*>(K + off);
      float4 kb = *reinterpret_cast<const float4*>(K + off + 4);
      uint4 oq, ok;
      oq.x = f2h2(qa.x, qa.y); oq.y = f2h2(qa.z, qa.w);
      oq.z = f2h2(qb.x, qb.y); oq.w = f2h2(qb.z, qb.w);
      ok.x = f2h2(ka.x, ka.y); ok.y = f2h2(ka.z, ka.w);
      ok.z = f2h2(kb.x, kb.y); ok.w = f2h2(kb.z, kb.w);
      *reinterpret_cast<uint4*>(g_Qh + off) = oq;
      *reinterpret_cast<uint4*>(g_Kh + off) = ok;
    }
    __threadfence();
    __syncthreads();
    if (tid == 0) atomicAdd(&g_c_aqk[b >> 4], 1);    // 16 blocks per 64-row group

  } else if (bx < B_AV) {
    // ============ Wv transpose: 4 tiles per block ============
    float* tile = reinterpret_cast<float*>(smem);
    const int b = bx - B_WV;               // 0..1023
    const int tx = tid & 31, ty = tid >> 5;
    #pragma unroll
    for (int tt = 0; tt < 4; ++tt) {
      const int t = b * 4 + tt;                      // 0..4095
      const int c0 = (t & 63) * 32, r0 = (t >> 6) * 32;
      __syncthreads();
      #pragma unroll
      for (int i = 0; i < 32; i += 8)
        tile[(ty + i) * 33 + tx] = Wv[(size_t)(r0 + ty + i) * Dd + (c0 + tx)];
      __syncthreads();
      #pragma unroll
      for (int i = 0; i < 32; i += 8)
        g_WvT[(size_t)(c0 + ty + i) * Dd + (r0 + tx)] =
            __float2half_rn(tile[tx * 33 + ty + i]);
    }
    __threadfence();
    __syncthreads();
    if (tid == 0) atomicAdd(&g_c_wv, 1);

  } else if (bx < B_QK) {
    // ============ V f2h: 8 rows per block ============
    const int b = bx - B_AV;               // 0..1023, rows 8b..8b+7
    #pragma unroll
    for (int r = 0; r < 8; ++r) {
      const size_t off = ((size_t)(b * 8 + r)) * Dd + tid * 8;
      float4 a = *reinterpret_cast<const float4*>(V + off);
      float4 c = *reinterpret_cast<const float4*>(V + off + 4);
      uint4 o;
      o.x = f2h2(a.x, a.y); o.y = f2h2(a.z, a.w);
      o.z = f2h2(c.x, c.y); o.w = f2h2(c.z, c.w);
      *reinterpret_cast<uint4*>(g_Vh + off) = o;
    }
    __threadfence();
    __syncthreads();
    if (tid == 0) atomicAdd(&g_c_av[b >> 4], 1);     // 16 blocks per 128-row group

  } else if (bx < B_V) {
    // ======================= QK gemm body (R16, verbatim) =======================
    const int bid = bx - B_QK;
    const int wid = tid >> 5, lane = tid & 31;
    const int g = lane >> 2, tig = lane & 3;
    const int l15 = lane & 15;
    const uint32_t aLane = (uint32_t)(l15 * ROWB) + ((lane >> 4) * 16);
    const int nbl = ((lane >> 4) & 1) * 8 + (lane & 7);
    const uint32_t bLane = (uint32_t)(nbl * ROWB) + (((lane >> 3) & 1) * 16);
    const int side = wid >> 2;
    const int w = wid & 3;
    const int mg = bid >> 3;
    const int m0 = mg * 64;
    const int n0 = (bid & 7) * 128;

    // wait for producers (all dispatched earlier)
    if (tid == 0) {
      waitc(&g_c_wqk, WQK_N);
      waitc(&g_c_aqk[mg], 16);
    }
    __syncthreads();
    __threadfence();

    auto load_stage = [&](int it, int s) {
      const int k0 = it * 64;
      const uint32_t base = sb + (uint32_t)s * QK_STAGE;
      #pragma unroll
      for (int i = 0; i < 4; ++i) {
        int ch = tid + i * 256;
        int r = ch >> 3, c = ch & 7;
        uint32_t off = (uint32_t)(r * ROWB + c * 16);
        const __half* src = (i < 2) ? (g_Qh + (size_t)(m0 + r) * Dd)
                                    : (g_Kh + (size_t)(m0 + r - 64) * Dd);
        cp16(base + off, src + k0 + c * 8);
      }
      #pragma unroll
      for (int i = 0; i < 8; ++i) {
        int ch = tid + i * 256;
        int r = ch >> 3, c = ch & 7;
        uint32_t off = (uint32_t)(128 * ROWB + r * ROWB + c * 16);
        const __half* src = (i < 4) ? (g_WqT + (size_t)(n0 + r) * Dd)
                                    : (g_WkT + (size_t)(n0 + r - 128) * Dd);
        cp16(base + off, src + k0 + c * 8);
      }
      cp_commit();
    };

    uint32_t aoff[4];
    #pragma unroll
    for (int i = 0; i < 4; ++i)
      aoff[i] = (uint32_t)((side * 64 + i * 16) * ROWB) + aLane;
    uint32_t boff[2];
    #pragma unroll
    for (int jp = 0; jp < 2; ++jp)
      boff[jp] = (uint32_t)((128 + side * 128 + w * 32 + jp * 16) * ROWB) + bLane;

    float cc[4][4][4];
    #pragma unroll
    for (int i = 0; i < 4; ++i)
      #pragma unroll
      for (int j = 0; j < 4; ++j)
        #pragma unroll
        for (int t = 0; t < 4; ++t) cc[i][j][t] = 0.f;

    load_stage(0, 0);

    const int NIT = Dd / 64;   // 32
    for (int it = 0; it < NIT; ++it) {
      cp_wait0();
      __syncthreads();
      if (it + 1 < NIT) load_stage(it + 1, (it + 1) & 1);

      const uint32_t stA = sb + (uint32_t)(it & 1) * QK_STAGE;
      #pragma unroll
      for (int ks = 0; ks < 4; ++ks) {
        const uint32_t kb = ks * 32;
        uint32_t a[4][4];
        ldsm4(a[0], stA + aoff[0] + kb);
        ldsm4(a[1], stA + aoff[1] + kb);
        ldsm4(a[2], stA + aoff[2] + kb);
        ldsm4(a[3], stA + aoff[3] + kb);
        uint32_t b[4][2];
        ldsm4(&b[0][0], stA + boff[0] + kb);
        ldsm4(&b[2][0], stA + boff[1] + kb);
        #pragma unroll
        for (int i = 0; i < 4; ++i)
          #pragma unroll
          for (int j = 0; j < 4; ++j)
            mma16(cc[i][j], a[i], b[j]);
      }
    }

    const float* bias = side ? bk : bq;
    float bb[4][2];
    #pragma unroll
    for (int j = 0; j < 4; ++j) {
      const int col = n0 + w * 32 + j * 8 + 2 * tig;
      bb[j][0] = bias[col]; bb[j][1] = bias[col + 1];
    }
    #pragma unroll
    for (int i = 0; i < 4; ++i) {
      float s0 = 0.f, s1 = 0.f;
      #pragma unroll
      for (int j = 0; j < 4; ++j) {
        cc[i][j][0] = elu_f(cc[i][j][0] + bb[j][0]);
        cc[i][j][1] = elu_f(cc[i][j][1] + bb[j][1]);
        cc[i][j][2] = elu_f(cc[i][j][2] + bb[j][0]);
        cc[i][j][3] = elu_f(cc[i][j][3] + bb[j][1]);
        s0 += cc[i][j][0] + cc[i][j][1];
        s1 += cc[i][j][2] + cc[i][j][3];
      }
      #pragma unroll
      for (int m = 1; m <= 2; m <<= 1) {
        s0 += __shfl_xor_sync(0xffffffffu, s0, m);
        s1 += __shfl_xor_sync(0xffffffffu, s1, m);
      }
      if (tig == 0) {
        float* arr = side ? g_sK : g_sQ;
        atomicAdd(&arr[m0 + i * 16 + g], s0);
        atomicAdd(&arr[m0 + i * 16 + g + 8], s1);
      }
    }
    __syncthreads();
    float* epi = reinterpret_cast<float*>(smem);
    if (side == 1) {
      #pragma unroll
      for (int i = 0; i < 4; ++i) {
        const int r0 = i * 16 + g, r1 = r0 + 8;
        #pragma unroll
        for (int j = 0; j < 4; ++j) {
          const int c = w * 32 + j * 8 + 2 * tig;
          *reinterpret_cast<float2*>(epi + r0 * EPIW + c) = make_float2(cc[i][j][0], cc[i][j][1]);
          *reinterpret_cast<float2*>(epi + r1 * EPIW + c) = make_float2(cc[i][j][2], cc[i][j][3]);
        }
      }
    }
    __syncthreads();
    if (side == 0) {
      #pragma unroll
      for (int i = 0; i < 4; ++i) {
        const int r0 = i * 16 + g, r1 = r0 + 8;
        float p0 = 0.f, p1 = 0.f;
        #pragma unroll
        for (int j = 0; j < 4; ++j) {
          const int c = w * 32 + j * 8 + 2 * tig;
          float2 k0v = *reinterpret_cast<const float2*>(epi + r0 * EPIW + c);
          float2 k1v = *reinterpret_cast<const float2*>(epi + r1 * EPIW + c);
          p0 += cc[i][j][0] * k0v.x + cc[i][j][1] * k0v.y;
          p1 += cc[i][j][2] * k1v.x + cc[i][j][3] * k1v.y;
        }
        #pragma unroll
        for (int m = 1; m <= 2; m <<= 1) {
          p0 += __shfl_xor_sync(0xffffffffu, p0, m);
          p1 += __shfl_xor_sync(0xffffffffu, p1, m);
        }
        if (tig == 0) {
          atomicAdd(&g_qk[m0 + i * 16 + g], p0);
          atomicAdd(&g_qk[m0 + i * 16 + g + 8], p1);
        }
      }
    }
    __threadfence();
    __syncthreads();
    if (tid == 0) atomicAdd(&g_done_m[mg], 1);

  } else {
    // ======================= V gemm body (R16, verbatim) =======================
    const int bid = bx - B_V;
    const int wid = tid >> 5, lane = tid & 31;
    const int g = lane >> 2, tig = lane & 3;
    const int l15 = lane & 15;
    const uint32_t aLane = (uint32_t)(l15 * ROWB) + ((lane >> 4) * 16);
    const int nbl = ((lane >> 4) & 1) * 8 + (lane & 7);
    const uint32_t bLane = (uint32_t)(nbl * ROWB) + (((lane >> 3) & 1) * 16);
    const int wm = wid >> 2, wn = wid & 3;
    const int m0 = (bid >> 4) * 128;
    const int n0 = (bid & 15) * 128;

    // wait for producers (all dispatched earlier)
    if (tid == 0) {
      waitc(&g_c_wv, WV_N);
      waitc(&g_c_av[bid >> 4], 16);
    }
    __syncthreads();
    __threadfence();

    auto load_stage = [&](int it, int s) {
      const int k0 = it * 64;
      const uint32_t base = sb + (uint32_t)s * V_STAGE;
      #pragma unroll
      for (int i = 0; i < 4; ++i) {
        int ch = tid + i * 256;
        int r = ch >> 3, c = ch & 7;
        uint32_t off = (uint32_t)(r * ROWB + c * 16);
        cp16(base + off,          g_Vh  + (size_t)(m0 + r) * Dd + k0 + c * 8);
        cp16(base + TILE_B + off, g_WvT + (size_t)(n0 + r) * Dd + k0 + c * 8);
      }
      cp_commit();
    };

    uint32_t aoff[4];
    #pragma unroll
    for (int i = 0; i < 4; ++i)
      aoff[i] = (uint32_t)((wm * 64 + i * 16) * ROWB) + aLane;
    uint32_t boff[2];
    #pragma unroll
    for (int jp = 0; jp < 2; ++jp)
      boff[jp] = (uint32_t)((wn * 32 + jp * 16) * ROWB) + bLane;

    float cc[4][4][4];
    #pragma unroll
    for (int i = 0; i < 4; ++i)
      #pragma unroll
      for (int j = 0; j < 4; ++j)
        #pragma unroll
        for (int t = 0; t < 4; ++t) cc[i][j][t] = 0.f;

    load_stage(0, 0);
    load_stage(1, 1);

    const int NIT = Dd / 64;   // 32
    for (int it = 0; it < NIT; ++it) {
      cp_wait1();
      __syncthreads();
      if (it + 2 < NIT) load_stage(it + 2, (it + 2) % 3);
      else cp_commit();

      const uint32_t stA = sb + (uint32_t)(it % 3) * V_STAGE;
      #pragma unroll
      for (int ks = 0; ks < 4; ++ks) {
        const uint32_t kb = ks * 32;
        uint32_t a[4][4];
        ldsm4(a[0], stA + aoff[0] + kb);
        ldsm4(a[1], stA + aoff[1] + kb);
        ldsm4(a[2], stA + aoff[2] + kb);
        ldsm4(a[3], stA + aoff[3] + kb);
        uint32_t b[4][2];
        ldsm4(&b[0][0], stA + TILE_B + boff[0] + kb);
        ldsm4(&b[2][0], stA + TILE_B + boff[1] + kb);
        #pragma unroll
        for (int i = 0; i < 4; ++i)
          #pragma unroll
          for (int j = 0; j < 4; ++j)
            mma16(cc[i][j], a[i], b[j]);
      }
    }

    // wait only for the QK blocks covering rows [m0, m0+128)
    if (tid == 0) {
      const int mg = 2 * (bid >> 4);
      waitc(&g_done_m[mg], N_PER_MG);
      waitc(&g_done_m[mg + 1], N_PER_MG);
    }
    __syncthreads();
    __threadfence();

    float bvc[4][2];
    #pragma unroll
    for (int j = 0; j < 4; ++j) {
      const int col = n0 + wn * 32 + j * 8 + 2 * tig;
      bvc[j][0] = bv[col]; bvc[j][1] = bv[col + 1];
    }
    #pragma unroll
    for (int i = 0; i < 4; ++i) {
      const int r0 = m0 + wm * 64 + i * 16 + g;
      const int r1 = r0 + 8;
      const float c0 = ldcg(&g_qk[r0]) / (ldcg(&g_sQ[r0]) * ldcg(&g_sK[r0]) + 1e-6f);
      const float c1 = ldcg(&g_qk[r1]) / (ldcg(&g_sQ[r1]) * ldcg(&g_sK[r1]) + 1e-6f);
      #pragma unroll
      for (int j = 0; j < 4; ++j) {
        const int col = n0 + wn * 32 + j * 8 + 2 * tig;
        float2 v0, v1;
        v0.x = c0 * (cc[i][j][0] + bvc[j][0]);
        v0.y = c0 * (cc[i][j][1] + bvc[j][1]);
        v1.x = c1 * (cc[i][j][2] + bvc[j][0]);
        v1.y = c1 * (cc[i][j][3] + bvc[j][1]);
        *reinterpret_cast<float2*>(out + (size_t)r0 * Dd + col) = v0;
        *reinterpret_cast<float2*>(out + (size_t)r1 * Dd + col) = v1;
      }
    }
  }
}

// ---------------- host launcher ----------------
extern "C" void kernel_launch(void* const* d_in, const int* /*in_sizes*/, int /*n_in*/,
                              void* d_out, int /*out_size*/) {
  const float* Q  = (const float*)d_in[0];
  const float* K  = (const float*)d_in[1];
  const float* V  = (const float*)d_in[2];
  const float* Wq = (const float*)d_in[3];
  const float* bq = (const float*)d_in[4];
  const float* Wk = (const float*)d_in[5];
  const float* bk = (const float*)d_in[6];
  const float* Wv = (const float*)d_in[7];
  const float* bv = (const float*)d_in[8];
  float* out = (float*)d_out;

  cudaFuncSetAttribute(mega_kernel, cudaFuncAttributeMaxDynamicSharedMemorySize, G_SMEM);

  init_kernel<<<Bn / 256, 256>>>();                                              // 0
  mega_kernel<<<TOTAL_BLOCKS, 256, G_SMEM>>>(Q, K, V, Wq, Wk, Wv,
                                             bq, bk, bv, out);                   // 1
}